// round 12
// baseline (speedup 1.0000x reference)
#include <cuda_runtime.h>
#include <cuda_bf16.h>
#include <cstdint>

#define B_DIM 16
#define C_DIM 64
#define K_DIM 207
#define L_DIM 64
#define KL    13248
#define C_IN  320
#define KSQ   (K_DIM * K_DIM)

// scratch
__device__ __nv_bfloat16 g_Mh[(size_t)B_DIM * 4 * 256 * 256];   // padded split M_t (0=A0,1=A0^2,2=A1,3=A1^2)
__device__ __nv_bfloat16 g_Ml[(size_t)B_DIM * 4 * 256 * 256];
__device__ __nv_bfloat16 g_Wh[320 * 64];                        // split W
__device__ __nv_bfloat16 g_Wl[320 * 64];
__device__ __nv_bfloat16 g_Xh[(size_t)B_DIM * C_DIM * KL];      // split x (same layout as x)
__device__ __nv_bfloat16 g_Xl[(size_t)B_DIM * C_DIM * KL];
__device__ __nv_bfloat16 g_Uh[(size_t)B_DIM * 4 * C_DIM * K_DIM * L_DIM];  // [b][t][o][k][l]
__device__ __nv_bfloat16 g_Ul[(size_t)B_DIM * 4 * C_DIM * K_DIM * L_DIM];

__device__ __forceinline__ uint32_t smem_u32(const void* p) {
    uint32_t a;
    asm("{ .reg .u64 t; cvta.to.shared.u64 t, %1; cvt.u32.u64 %0, t; }" : "=r"(a) : "l"(p));
    return a;
}
__device__ __forceinline__ void split2(float v, __nv_bfloat16& h, __nv_bfloat16& l) {
    h = __float2bfloat16(v);
    l = __float2bfloat16(v - __bfloat162float(h));
}
__device__ __forceinline__ void ldsm4(uint32_t* r, uint32_t addr) {
    asm volatile("ldmatrix.sync.aligned.m8n8.x4.shared.b16 {%0,%1,%2,%3}, [%4];"
                 : "=r"(r[0]), "=r"(r[1]), "=r"(r[2]), "=r"(r[3]) : "r"(addr));
}
__device__ __forceinline__ void ldsm4t(uint32_t* r, uint32_t addr) {
    asm volatile("ldmatrix.sync.aligned.m8n8.x4.trans.shared.b16 {%0,%1,%2,%3}, [%4];"
                 : "=r"(r[0]), "=r"(r[1]), "=r"(r[2]), "=r"(r[3]) : "r"(addr));
}
__device__ __forceinline__ void mma16816(float* d, const uint32_t* a, const uint32_t* b) {
    asm volatile(
        "mma.sync.aligned.m16n8k16.row.col.f32.bf16.bf16.f32 "
        "{%0,%1,%2,%3}, {%4,%5,%6,%7}, {%8,%9}, {%0,%1,%2,%3};"
        : "+f"(d[0]), "+f"(d[1]), "+f"(d[2]), "+f"(d[3])
        : "r"(a[0]), "r"(a[1]), "r"(a[2]), "r"(a[3]), "r"(b[0]), "r"(b[1]));
}
__device__ __forceinline__ void cpa16(uint32_t dst, const void* src) {
    asm volatile("cp.async.cg.shared.global [%0], [%1], 16;" :: "r"(dst), "l"(src));
}
__device__ __forceinline__ void cpa16z(uint32_t dst, const void* src, int sz) {
    asm volatile("cp.async.cg.shared.global [%0], [%1], 16, %2;" :: "r"(dst), "l"(src), "r"(sz));
}
#define CP_COMMIT() asm volatile("cp.async.commit_group;" ::: "memory")
#define CP_WAIT0()  asm volatile("cp.async.wait_group 0;" ::: "memory")
#define CP_WAIT1()  asm volatile("cp.async.wait_group 1;" ::: "memory")

// ---------------------------------------------------------------- split A0/A1 into padded planes (slots 0, 2)
__global__ __launch_bounds__(256)
void splitM_kernel(const float* __restrict__ a0, const float* __restrict__ a1) {
    size_t e = (size_t)blockIdx.x * 256 + threadIdx.x;   // 2*16*65536 total
    int k = (int)(e & 255), j = (int)((e >> 8) & 255);
    int which = (int)((e >> 16) & 1), b = (int)(e >> 17);
    float v = 0.f;
    if (j < K_DIM && k < K_DIM) {
        const float* M = (which ? a1 : a0) + (size_t)b * KSQ;
        v = M[(size_t)j * K_DIM + k];
    }
    __nv_bfloat16 h, l; split2(v, h, l);
    size_t idx = (((size_t)(b * 4 + which * 2)) << 16) + ((size_t)j << 8) + k;
    g_Mh[idx] = h; g_Ml[idx] = l;
}

__global__ __launch_bounds__(256)
void splitW_kernel(const float* __restrict__ W) {
    int e = blockIdx.x * 256 + threadIdx.x;
    if (e < 320 * 64) {
        int m = e >> 6, c = e & 63;
        int t = m >> 6, o = m & 63;
        float v = W[(size_t)o * C_IN + t * 64 + c];
        __nv_bfloat16 h, l; split2(v, h, l);
        g_Wh[e] = h; g_Wl[e] = l;
    }
}

// ---------------------------------------------------------------- split x (flat map; same layout)
__global__ __launch_bounds__(256)
void splitX_kernel(const float* __restrict__ x) {
    size_t e = (size_t)blockIdx.x * 256 + threadIdx.x;   // 16*64*13248 = 13565952
    __nv_bfloat16 h, l; split2(x[e], h, l);
    g_Xh[e] = h; g_Xl[e] = l;
}

// ---------------------------------------------------------------- square via MMA: slot t+1 = (slot t)^2
// Block (nhalf, which, b): D[j, n] = sum_m A[j,m] A[m,n], n in [nhalf*128, +128)
#define SQ_AH 0
#define SQ_AL 36864
#define SQ_BH 73728
#define SQ_BL 91136
#define SQ_SMEM 108544

__global__ __launch_bounds__(512)
void square_mma() {
    extern __shared__ __align__(16) char smem[];
    const int tid = threadIdx.x, lane = tid & 31, w = tid >> 5;
    const int nh = blockIdx.x, which = blockIdx.y, b = blockIdx.z;
    const int tslot = which * 2;
    const uint32_t sb = smem_u32(smem);
    const char* Mh = (const char*)(g_Mh + ((size_t)(b * 4 + tslot) << 16));
    const char* Ml = (const char*)(g_Ml + ((size_t)(b * 4 + tslot) << 16));

    float acc[16][4];
    #pragma unroll
    for (int i = 0; i < 16; ++i)
        #pragma unroll
        for (int q = 0; q < 4; ++q) acc[i][q] = 0.f;

    const int rowA = lane & 15, colA = (lane >> 4) * 8;
    const int rowB = lane & 15, colB = (lane >> 4) * 8;

    for (int kc = 0; kc < 4; ++kc) {
        #pragma unroll
        for (int it = 0; it < 8; ++it) {
            int e = tid + it * 512;
            int pl = e >> 11, rem = e & 2047;
            int r = rem >> 3, u = rem & 7;
            const char* src = (pl ? Ml : Mh) + r * 512 + kc * 128 + u * 16;
            cpa16(sb + (pl ? SQ_AL : SQ_AH) + r * 144 + u * 16, src);
        }
        #pragma unroll
        for (int it = 0; it < 4; ++it) {
            int e = tid + it * 512;
            int pl = e >> 10, rem = e & 1023;
            int r = rem >> 4, u = rem & 15;
            const char* src = (pl ? Ml : Mh) + (kc * 64 + r) * 512 + nh * 256 + u * 16;
            cpa16(sb + (pl ? SQ_BL : SQ_BH) + r * 272 + u * 16, src);
        }
        CP_COMMIT();
        CP_WAIT0();
        __syncthreads();

        #pragma unroll
        for (int c0 = 0; c0 < 64; c0 += 16) {
            uint32_t ah[4], al[4];
            uint32_t ra = sb + SQ_AH + (uint32_t)(((w * 16 + rowA) * 72 + c0 + colA) * 2);
            ldsm4(ah, ra);
            ldsm4(al, ra + (SQ_AL - SQ_AH));
            #pragma unroll
            for (int p = 0; p < 8; ++p) {
                uint32_t bh[4], bl[4];
                uint32_t rb = sb + SQ_BH + (uint32_t)(((c0 + rowB) * 136 + p * 16 + colB) * 2);
                ldsm4t(bh, rb);
                ldsm4t(bl, rb + (SQ_BL - SQ_BH));
                #pragma unroll
                for (int jj = 0; jj < 2; ++jj) {
                    float* d = acc[p * 2 + jj];
                    mma16816(d, ah, &bh[jj * 2]);
                    mma16816(d, ah, &bl[jj * 2]);
                    mma16816(d, al, &bh[jj * 2]);
                }
            }
        }
        __syncthreads();
    }

    uint32_t* Dh = (uint32_t*)(g_Mh + ((size_t)(b * 4 + tslot + 1) << 16));
    uint32_t* Dl = (uint32_t*)(g_Ml + ((size_t)(b * 4 + tslot + 1) << 16));
    #pragma unroll
    for (int rsel = 0; rsel < 2; ++rsel) {
        const int j = w * 16 + (lane >> 2) + rsel * 8;
        #pragma unroll
        for (int i = 0; i < 16; ++i) {
            int n = nh * 128 + i * 8 + (lane & 3) * 2;
            __nv_bfloat16 h0, l0, h1, l1;
            split2(acc[i][rsel * 2], h0, l0);
            split2(acc[i][rsel * 2 + 1], h1, l1);
            Dh[(j * 256 + n) >> 1] = (uint32_t)__bfloat16_as_ushort(h0) |
                                     ((uint32_t)__bfloat16_as_ushort(h1) << 16);
            Dl[(j * 256 + n) >> 1] = (uint32_t)__bfloat16_as_ushort(l0) |
                                     ((uint32_t)__bfloat16_as_ushort(l1) << 16);
        }
    }
}

// ---------------------------------------------------------------- Stage B
// 3-deep x pipeline, one __syncthreads per k-column. x pre-split in global.
#define BW_H 0
#define BW_L 46080
#define BX(buf) (92160 + (buf) * 18432)    // per buf: h at +0, l at +9216
#define B_SMEM 147456
#define KGRP 8

__global__ __launch_bounds__(640)
void chanmix_mma(const float* __restrict__ bias, float* __restrict__ out) {
    extern __shared__ __align__(16) char smem[];
    const int tid = threadIdx.x, lane = tid & 31, w = tid >> 5;
    const int b = blockIdx.y;
    const int kbase = blockIdx.x * KGRP;
    const int G = (kbase + KGRP <= K_DIM) ? KGRP : (K_DIM - kbase);
    const uint32_t sb = smem_u32(smem);

    // stage W — once per block
    #pragma unroll
    for (int it = 0; it < 4; ++it) {
        int e = tid + it * 640;
        if (e < 2560) {
            int r = e >> 3, u = e & 7;
            cpa16(sb + BW_H + r * 144 + u * 16, (const char*)g_Wh + r * 128 + u * 16);
            cpa16(sb + BW_L + r * 144 + u * 16, (const char*)g_Wl + r * 128 + u * 16);
        }
    }
    CP_COMMIT();

    auto stageX = [&](int ki) {
        const int kcol2 = kbase + ki;
        #pragma unroll
        for (int it = 0; it < 2; ++it) {
            int e = tid + it * 640;
            if (e < 1024) {
                int pl = e >> 9, rem = e & 511;
                int c = rem >> 3, u = rem & 7;
                const char* src = (const char*)(pl ? g_Xl : g_Xh)
                    + ((size_t)(b * 64 + c) * KL + (size_t)kcol2 * 64) * 2 + u * 16;
                cpa16(sb + BX(ki % 3) + pl * 9216 + c * 144 + u * 16, src);
            }
        }
    };

    stageX(0); CP_COMMIT();
    if (G > 1) { stageX(1); CP_COMMIT(); }

    const int rowA = lane & 15, colA = (lane >> 4) * 8;
    const int rowB = lane & 15, colB = (lane >> 4) * 8;

    for (int ki = 0; ki < G; ++ki) {
        const int kcol = kbase + ki;
        if (ki + 1 < G) CP_WAIT1(); else CP_WAIT0();
        __syncthreads();                       // all warps done with buf (ki-1)%3 readers
        if (ki + 2 < G) { stageX(ki + 2); CP_COMMIT(); }

        float acc[8][4];
        #pragma unroll
        for (int j = 0; j < 8; ++j)
            #pragma unroll
            for (int q = 0; q < 4; ++q) acc[j][q] = 0.f;

        const uint32_t xbase = sb + BX(ki % 3);
        #pragma unroll
        for (int c0 = 0; c0 < 64; c0 += 16) {
            uint32_t ah[4], al[4];
            uint32_t ra = sb + BW_H + (uint32_t)(((w * 16 + rowA) * 72 + c0 + colA) * 2);
            ldsm4(ah, ra);
            ldsm4(al, ra + (BW_L - BW_H));
            #pragma unroll
            for (int p = 0; p < 4; ++p) {
                uint32_t bh[4], bl[4];
                uint32_t rb = xbase + (uint32_t)(((c0 + rowB) * 72 + p * 16 + colB) * 2);
                ldsm4t(bh, rb);
                ldsm4t(bl, rb + 9216);
                #pragma unroll
                for (int jj = 0; jj < 2; ++jj) {
                    float* d = acc[p * 2 + jj];
                    mma16816(d, ah, &bh[jj * 2]);
                    mma16816(d, ah, &bl[jj * 2]);
                    mma16816(d, al, &bh[jj * 2]);
                }
            }
        }

        #pragma unroll
        for (int rsel = 0; rsel < 2; ++rsel) {
            const int m = w * 16 + (lane >> 2) + rsel * 8;
            const int t = m >> 6, o = m & 63;
            if (t == 0) {
                const float bo = bias[o];
                float* op = out + ((size_t)b * 64 + o) * KL + (size_t)kcol * 64;
                #pragma unroll
                for (int n8 = 0; n8 < 8; ++n8) {
                    int l = n8 * 8 + (lane & 3) * 2;
                    *(float2*)(op + l) = make_float2(acc[n8][rsel * 2] + bo,
                                                     acc[n8][rsel * 2 + 1] + bo);
                }
            } else {
                const size_t rb2 = ((((size_t)b * 4 + (t - 1)) * 64 + o) * K_DIM + kcol) * 64;
                uint32_t* Uhp = (uint32_t*)(g_Uh + rb2);
                uint32_t* Ulp = (uint32_t*)(g_Ul + rb2);
                #pragma unroll
                for (int n8 = 0; n8 < 8; ++n8) {
                    int l = n8 * 8 + (lane & 3) * 2;
                    __nv_bfloat16 h0, l0, h1, l1;
                    split2(acc[n8][rsel * 2], h0, l0);
                    split2(acc[n8][rsel * 2 + 1], h1, l1);
                    Uhp[l >> 1] = (uint32_t)__bfloat16_as_ushort(h0) |
                                  ((uint32_t)__bfloat16_as_ushort(h1) << 16);
                    Ulp[l >> 1] = (uint32_t)__bfloat16_as_ushort(l0) |
                                  ((uint32_t)__bfloat16_as_ushort(l1) << 16);
                }
            }
        }
    }
}

// ---------------------------------------------------------------- Stage C (unchanged from R11)
#define C_AH 0
#define C_AL 29952
#define C_BH 59904          // + oi*9216
#define C_BL 78336          // + oi*9216
#define CBUF 96768
#define C_SMEM (2 * CBUF)

__global__ __launch_bounds__(512)
void diffuse_mma(float* __restrict__ out) {
    extern __shared__ __align__(16) char smem[];
    const int tid = threadIdx.x, lane = tid & 31, w = tid >> 5;
    const int b = blockIdx.y, o0 = blockIdx.x * 2;
    const uint32_t sb = smem_u32(smem);

    float acc[2][8][4];
    #pragma unroll
    for (int oi = 0; oi < 2; ++oi)
        #pragma unroll
        for (int j = 0; j < 8; ++j)
            #pragma unroll
            for (int q = 0; q < 4; ++q) acc[oi][j][q] = 0.f;

    const int rowA = lane & 15, colA = (lane >> 4) * 8;
    const int rowB = lane & 15, colB = (lane >> 4) * 8;

    auto stage = [&](int s, int buf) {
        const int t = s >> 2, kc = s & 3;
        const char* Mh = (const char*)(g_Mh + ((size_t)(b * 4 + t) << 16));
        const char* Ml = (const char*)(g_Ml + ((size_t)(b * 4 + t) << 16));
        const uint32_t base = sb + buf * CBUF;
        #pragma unroll
        for (int it = 0; it < 7; ++it) {
            int e = tid + it * 512;
            if (e < 3328) {
                int pl = e / 1664, rem = e - pl * 1664;
                int r = rem >> 3, u = rem & 7;
                const char* src = (pl ? Ml : Mh) + r * 512 + kc * 128 + u * 16;
                cpa16(base + (pl ? C_AL : C_AH) + r * 144 + u * 16, src);
            }
        }
        #pragma unroll
        for (int it = 0; it < 4; ++it) {
            int e = tid + it * 512;
            int oi = e >> 10, rem = e & 1023;
            int pl = rem >> 9, r = (rem >> 3) & 63, u = rem & 7;
            int kg = kc * 64 + r;
            int sz = (kg < K_DIM) ? 16 : 0;
            const char* Ub = (const char*)(pl ? g_Ul : g_Uh) +
                ((((size_t)b * 4 + t) * 64 + o0 + oi) * K_DIM) * 128;
            size_t so = (size_t)((kg < K_DIM) ? kg : 0) * 128 + u * 16;
            cpa16z(base + (pl ? C_BL : C_BH) + oi * 9216 + r * 144 + u * 16, Ub + so, sz);
        }
        CP_COMMIT();
    };

    stage(0, 0);
    for (int s = 0; s < 16; ++s) {
        if (s + 1 < 16) { stage(s + 1, (s + 1) & 1); CP_WAIT1(); }
        else            { CP_WAIT0(); }
        __syncthreads();
        const uint32_t base = sb + (s & 1) * CBUF;
        if (w < 13) {
            const int c0max = ((s & 3) == 3) ? 16 : 64;
            for (int c0 = 0; c0 < c0max; c0 += 16) {
                uint32_t ah[4], al[4];
                uint32_t ra = base + C_AH + (uint32_t)(((w * 16 + rowA) * 72 + c0 + colA) * 2);
                ldsm4(ah, ra);
                ldsm4(al, ra + (C_AL - C_AH));
                #pragma unroll
                for (int oi = 0; oi < 2; ++oi) {
                    #pragma unroll
                    for (int p = 0; p < 4; ++p) {
                        uint32_t bh[4], bl[4];
                        uint32_t rb = base + C_BH + oi * 9216 +
                                      (uint32_t)(((c0 + rowB) * 72 + p * 16 + colB) * 2);
                        ldsm4t(bh, rb);
                        ldsm4t(bl, rb + (C_BL - C_BH));
                        #pragma unroll
                        for (int jj = 0; jj < 2; ++jj) {
                            float* d = acc[oi][p * 2 + jj];
                            mma16816(d, ah, &bh[jj * 2]);
                            mma16816(d, ah, &bl[jj * 2]);
                            mma16816(d, al, &bh[jj * 2]);
                        }
                    }
                }
            }
        }
        __syncthreads();
    }

    #pragma unroll
    for (int oi = 0; oi < 2; ++oi) {
        float* ob = out + ((size_t)b * 64 + o0 + oi) * KL;
        #pragma unroll
        for (int rsel = 0; rsel < 2; ++rsel) {
            const int j = w * 16 + (lane >> 2) + rsel * 8;
            if (j < K_DIM) {
                float* op = ob + (size_t)j * 64;
                #pragma unroll
                for (int n8 = 0; n8 < 8; ++n8) {
                    int l = n8 * 8 + (lane & 3) * 2;
                    float2 u = *(float2*)(op + l);
                    u.x += acc[oi][n8][rsel * 2];
                    u.y += acc[oi][n8][rsel * 2 + 1];
                    *(float2*)(op + l) = u;
                }
            }
        }
    }
}

// ----------------------------------------------------------------
extern "C" void kernel_launch(void* const* d_in, const int* in_sizes, int n_in,
                              void* d_out, int out_size) {
    (void)in_sizes; (void)n_in; (void)out_size;
    const float* x    = (const float*)d_in[0];
    const float* a0   = (const float*)d_in[1];
    const float* a1   = (const float*)d_in[2];
    const float* W    = (const float*)d_in[3];
    const float* bias = (const float*)d_in[4];
    float* out        = (float*)d_out;

    cudaFuncSetAttribute(square_mma, cudaFuncAttributeMaxDynamicSharedMemorySize, SQ_SMEM);
    cudaFuncSetAttribute(chanmix_mma, cudaFuncAttributeMaxDynamicSharedMemorySize, B_SMEM);
    cudaFuncSetAttribute(diffuse_mma, cudaFuncAttributeMaxDynamicSharedMemorySize, C_SMEM);

    splitM_kernel<<<8192, 256>>>(a0, a1);
    splitW_kernel<<<80, 256>>>(W);
    splitX_kernel<<<52992, 256>>>(x);
    {
        dim3 grid(2, 2, B_DIM);    // nhalf x which x b
        square_mma<<<grid, 512, SQ_SMEM>>>();
    }
    {
        dim3 grid((K_DIM + KGRP - 1) / KGRP, B_DIM);   // 26 x 16
        chanmix_mma<<<grid, 640, B_SMEM>>>(bias, out);
    }
    {
        dim3 grid(C_DIM / 2, B_DIM);   // 32 x 16
        diffuse_mma<<<grid, 512, C_SMEM>>>(out);
    }
}

// round 13
// speedup vs baseline: 1.1604x; 1.1604x over previous
#include <cuda_runtime.h>
#include <cuda_bf16.h>
#include <cstdint>

#define B_DIM 16
#define C_DIM 64
#define K_DIM 207
#define L_DIM 64
#define KL    13248
#define C_IN  320
#define KSQ   (K_DIM * K_DIM)

// scratch
__device__ __nv_bfloat16 g_Mh[(size_t)B_DIM * 4 * 256 * 256];   // padded split M_t (0=A0,1=A0^2,2=A1,3=A1^2)
__device__ __nv_bfloat16 g_Ml[(size_t)B_DIM * 4 * 256 * 256];
__device__ __nv_bfloat16 g_Wh[320 * 64];                        // split W
__device__ __nv_bfloat16 g_Wl[320 * 64];
__device__ __nv_bfloat16 g_Uh[(size_t)B_DIM * 4 * C_DIM * K_DIM * L_DIM];  // [b][t][o][k][l]
__device__ __nv_bfloat16 g_Ul[(size_t)B_DIM * 4 * C_DIM * K_DIM * L_DIM];

__device__ __forceinline__ uint32_t smem_u32(const void* p) {
    uint32_t a;
    asm("{ .reg .u64 t; cvta.to.shared.u64 t, %1; cvt.u32.u64 %0, t; }" : "=r"(a) : "l"(p));
    return a;
}
__device__ __forceinline__ void split2(float v, __nv_bfloat16& h, __nv_bfloat16& l) {
    h = __float2bfloat16(v);
    l = __float2bfloat16(v - __bfloat162float(h));
}
__device__ __forceinline__ void ldsm4(uint32_t* r, uint32_t addr) {
    asm volatile("ldmatrix.sync.aligned.m8n8.x4.shared.b16 {%0,%1,%2,%3}, [%4];"
                 : "=r"(r[0]), "=r"(r[1]), "=r"(r[2]), "=r"(r[3]) : "r"(addr));
}
__device__ __forceinline__ void ldsm4t(uint32_t* r, uint32_t addr) {
    asm volatile("ldmatrix.sync.aligned.m8n8.x4.trans.shared.b16 {%0,%1,%2,%3}, [%4];"
                 : "=r"(r[0]), "=r"(r[1]), "=r"(r[2]), "=r"(r[3]) : "r"(addr));
}
__device__ __forceinline__ void mma16816(float* d, const uint32_t* a, const uint32_t* b) {
    asm volatile(
        "mma.sync.aligned.m16n8k16.row.col.f32.bf16.bf16.f32 "
        "{%0,%1,%2,%3}, {%4,%5,%6,%7}, {%8,%9}, {%0,%1,%2,%3};"
        : "+f"(d[0]), "+f"(d[1]), "+f"(d[2]), "+f"(d[3])
        : "r"(a[0]), "r"(a[1]), "r"(a[2]), "r"(a[3]), "r"(b[0]), "r"(b[1]));
}
__device__ __forceinline__ void cpa16(uint32_t dst, const void* src) {
    asm volatile("cp.async.cg.shared.global [%0], [%1], 16;" :: "r"(dst), "l"(src));
}
__device__ __forceinline__ void cpa16z(uint32_t dst, const void* src, int sz) {
    asm volatile("cp.async.cg.shared.global [%0], [%1], 16, %2;" :: "r"(dst), "l"(src), "r"(sz));
}
#define CP_COMMIT() asm volatile("cp.async.commit_group;" ::: "memory")
#define CP_WAIT0()  asm volatile("cp.async.wait_group 0;" ::: "memory")
#define CP_WAIT1()  asm volatile("cp.async.wait_group 1;" ::: "memory")

// ---------------------------------------------------------------- split A0/A1 into padded planes (slots 0, 2)
__global__ __launch_bounds__(256)
void splitM_kernel(const float* __restrict__ a0, const float* __restrict__ a1) {
    size_t e = (size_t)blockIdx.x * 256 + threadIdx.x;   // 2*16*65536 total
    int k = (int)(e & 255), j = (int)((e >> 8) & 255);
    int which = (int)((e >> 16) & 1), b = (int)(e >> 17);
    float v = 0.f;
    if (j < K_DIM && k < K_DIM) {
        const float* M = (which ? a1 : a0) + (size_t)b * KSQ;
        v = M[(size_t)j * K_DIM + k];
    }
    __nv_bfloat16 h, l; split2(v, h, l);
    size_t idx = (((size_t)(b * 4 + which * 2)) << 16) + ((size_t)j << 8) + k;
    g_Mh[idx] = h; g_Ml[idx] = l;
}

__global__ __launch_bounds__(256)
void splitW_kernel(const float* __restrict__ W) {
    int e = blockIdx.x * 256 + threadIdx.x;
    if (e < 320 * 64) {
        int m = e >> 6, c = e & 63;
        int t = m >> 6, o = m & 63;
        float v = W[(size_t)o * C_IN + t * 64 + c];
        __nv_bfloat16 h, l; split2(v, h, l);
        g_Wh[e] = h; g_Wl[e] = l;
    }
}

// ---------------------------------------------------------------- square via MMA: slot t+1 = (slot t)^2
#define SQ_AH 0
#define SQ_AL 36864
#define SQ_BH 73728
#define SQ_BL 91136
#define SQ_SMEM 108544

__global__ __launch_bounds__(512)
void square_mma() {
    extern __shared__ __align__(16) char smem[];
    const int tid = threadIdx.x, lane = tid & 31, w = tid >> 5;
    const int nh = blockIdx.x, which = blockIdx.y, b = blockIdx.z;
    const int tslot = which * 2;
    const uint32_t sb = smem_u32(smem);
    const char* Mh = (const char*)(g_Mh + ((size_t)(b * 4 + tslot) << 16));
    const char* Ml = (const char*)(g_Ml + ((size_t)(b * 4 + tslot) << 16));

    float acc[16][4];
    #pragma unroll
    for (int i = 0; i < 16; ++i)
        #pragma unroll
        for (int q = 0; q < 4; ++q) acc[i][q] = 0.f;

    const int rowA = lane & 15, colA = (lane >> 4) * 8;
    const int rowB = lane & 15, colB = (lane >> 4) * 8;

    for (int kc = 0; kc < 4; ++kc) {
        #pragma unroll
        for (int it = 0; it < 8; ++it) {
            int e = tid + it * 512;
            int pl = e >> 11, rem = e & 2047;
            int r = rem >> 3, u = rem & 7;
            const char* src = (pl ? Ml : Mh) + r * 512 + kc * 128 + u * 16;
            cpa16(sb + (pl ? SQ_AL : SQ_AH) + r * 144 + u * 16, src);
        }
        #pragma unroll
        for (int it = 0; it < 4; ++it) {
            int e = tid + it * 512;
            int pl = e >> 10, rem = e & 1023;
            int r = rem >> 4, u = rem & 15;
            const char* src = (pl ? Ml : Mh) + (kc * 64 + r) * 512 + nh * 256 + u * 16;
            cpa16(sb + (pl ? SQ_BL : SQ_BH) + r * 272 + u * 16, src);
        }
        CP_COMMIT();
        CP_WAIT0();
        __syncthreads();

        #pragma unroll
        for (int c0 = 0; c0 < 64; c0 += 16) {
            uint32_t ah[4], al[4];
            uint32_t ra = sb + SQ_AH + (uint32_t)(((w * 16 + rowA) * 72 + c0 + colA) * 2);
            ldsm4(ah, ra);
            ldsm4(al, ra + (SQ_AL - SQ_AH));
            #pragma unroll
            for (int p = 0; p < 8; ++p) {
                uint32_t bh[4], bl[4];
                uint32_t rb = sb + SQ_BH + (uint32_t)(((c0 + rowB) * 136 + p * 16 + colB) * 2);
                ldsm4t(bh, rb);
                ldsm4t(bl, rb + (SQ_BL - SQ_BH));
                #pragma unroll
                for (int jj = 0; jj < 2; ++jj) {
                    float* d = acc[p * 2 + jj];
                    mma16816(d, ah, &bh[jj * 2]);
                    mma16816(d, ah, &bl[jj * 2]);
                    mma16816(d, al, &bh[jj * 2]);
                }
            }
        }
        __syncthreads();
    }

    uint32_t* Dh = (uint32_t*)(g_Mh + ((size_t)(b * 4 + tslot + 1) << 16));
    uint32_t* Dl = (uint32_t*)(g_Ml + ((size_t)(b * 4 + tslot + 1) << 16));
    #pragma unroll
    for (int rsel = 0; rsel < 2; ++rsel) {
        const int j = w * 16 + (lane >> 2) + rsel * 8;
        #pragma unroll
        for (int i = 0; i < 16; ++i) {
            int n = nh * 128 + i * 8 + (lane & 3) * 2;
            __nv_bfloat16 h0, l0, h1, l1;
            split2(acc[i][rsel * 2], h0, l0);
            split2(acc[i][rsel * 2 + 1], h1, l1);
            Dh[(j * 256 + n) >> 1] = (uint32_t)__bfloat16_as_ushort(h0) |
                                     ((uint32_t)__bfloat16_as_ushort(h1) << 16);
            Dl[(j * 256 + n) >> 1] = (uint32_t)__bfloat16_as_ushort(l0) |
                                     ((uint32_t)__bfloat16_as_ushort(l1) << 16);
        }
    }
}

// ---------------------------------------------------------------- Stage B
// fp32 x staging + convert (R11 proven) + smem-bounce coalesced U epilogue.
#define BW_H 0
#define BW_L 46080
#define BXF(buf)  (92160 + (buf) * 16384)
#define BXB(buf)  (124928 + (buf) * 18432)
#define B_BNC 161792                     // 20 warps x 2304 B
#define B_SMEM 207872
#define KGRP 8

__global__ __launch_bounds__(640)
void chanmix_mma(const float* __restrict__ x, const float* __restrict__ bias,
                 float* __restrict__ out) {
    extern __shared__ __align__(16) char smem[];
    const int tid = threadIdx.x, lane = tid & 31, w = tid >> 5;
    const int b = blockIdx.y;
    const int kbase = blockIdx.x * KGRP;
    const int G = (kbase + KGRP <= K_DIM) ? KGRP : (K_DIM - kbase);
    const uint32_t sb = smem_u32(smem);
    const float* xb = x + (size_t)b * C_DIM * KL;

    #pragma unroll
    for (int it = 0; it < 4; ++it) {
        int e = tid + it * 640;
        if (e < 2560) {
            int r = e >> 3, u = e & 7;
            cpa16(sb + BW_H + r * 144 + u * 16, (const char*)g_Wh + r * 128 + u * 16);
            cpa16(sb + BW_L + r * 144 + u * 16, (const char*)g_Wl + r * 128 + u * 16);
        }
    }
    CP_COMMIT();

    {
        int e = tid;
        #pragma unroll
        for (int it = 0; it < 2; ++it, e += 640)
            if (e < 1024) {
                int c = e >> 4, u = e & 15;
                cpa16(sb + BXF(0) + c * 256 + u * 16,
                      (const char*)(xb + (size_t)c * KL + (size_t)kbase * 64) + u * 16);
            }
        CP_COMMIT();
    }

    const int rowA = lane & 15, colA = (lane >> 4) * 8;
    const int rowB = lane & 15, colB = (lane >> 4) * 8;
    const int m0r = w * 16;
    const int twarp = m0r >> 6;

    for (int ki = 0; ki < G; ++ki) {
        const int kcol = kbase + ki;
        if (ki + 1 < G) {
            int e = tid;
            #pragma unroll
            for (int it = 0; it < 2; ++it, e += 640)
                if (e < 1024) {
                    int c = e >> 4, u = e & 15;
                    cpa16(sb + BXF((ki + 1) & 1) + c * 256 + u * 16,
                          (const char*)(xb + (size_t)c * KL + (size_t)(kcol + 1) * 64) + u * 16);
                }
            CP_COMMIT();
            CP_WAIT1();
        } else {
            CP_WAIT0();
        }
        __syncthreads();

        {
            const float4* fs = (const float4*)(smem + BXF(ki & 1));
            char* bh = smem + BXB(ki & 1);
            int e = tid;
            #pragma unroll
            for (int it = 0; it < 2; ++it, e += 640)
                if (e < 1024) {
                    int c = e >> 4, q = e & 15;
                    float4 v = fs[c * 16 + q];
                    __nv_bfloat16 h0, l0, h1, l1, h2, l2, h3, l3;
                    split2(v.x, h0, l0); split2(v.y, h1, l1);
                    split2(v.z, h2, l2); split2(v.w, h3, l3);
                    uint2 ph, pl;
                    ph.x = (uint32_t)__bfloat16_as_ushort(h0) | ((uint32_t)__bfloat16_as_ushort(h1) << 16);
                    ph.y = (uint32_t)__bfloat16_as_ushort(h2) | ((uint32_t)__bfloat16_as_ushort(h3) << 16);
                    pl.x = (uint32_t)__bfloat16_as_ushort(l0) | ((uint32_t)__bfloat16_as_ushort(l1) << 16);
                    pl.y = (uint32_t)__bfloat16_as_ushort(l2) | ((uint32_t)__bfloat16_as_ushort(l3) << 16);
                    *(uint2*)(bh + c * 144 + q * 8) = ph;
                    *(uint2*)(bh + 9216 + c * 144 + q * 8) = pl;
                }
        }
        __syncthreads();

        float acc[8][4];
        #pragma unroll
        for (int j = 0; j < 8; ++j)
            #pragma unroll
            for (int q = 0; q < 4; ++q) acc[j][q] = 0.f;

        const uint32_t xbase = sb + BXB(ki & 1);
        #pragma unroll
        for (int c0 = 0; c0 < 64; c0 += 16) {
            uint32_t ah[4], al[4];
            uint32_t ra = sb + BW_H + (uint32_t)(((m0r + rowA) * 72 + c0 + colA) * 2);
            ldsm4(ah, ra);
            ldsm4(al, ra + (BW_L - BW_H));
            #pragma unroll
            for (int p = 0; p < 4; ++p) {
                uint32_t bh[4], bl[4];
                uint32_t rb = xbase + (uint32_t)(((c0 + rowB) * 72 + p * 16 + colB) * 2);
                ldsm4t(bh, rb);
                ldsm4t(bl, rb + 9216);
                #pragma unroll
                for (int jj = 0; jj < 2; ++jj) {
                    float* d = acc[p * 2 + jj];
                    mma16816(d, ah, &bh[jj * 2]);
                    mma16816(d, ah, &bl[jj * 2]);
                    mma16816(d, al, &bh[jj * 2]);
                }
            }
        }

        // ---------------- epilogue ----------------
        if (twarp == 0) {
            // t = 0: direct fp32 stores with bias
            #pragma unroll
            for (int rsel = 0; rsel < 2; ++rsel) {
                const int o = (m0r + (lane >> 2) + rsel * 8) & 63;
                const float bo = bias[o];
                float* op = out + ((size_t)b * 64 + o) * KL + (size_t)kcol * 64;
                #pragma unroll
                for (int n8 = 0; n8 < 8; ++n8) {
                    int l = n8 * 8 + (lane & 3) * 2;
                    *(float2*)(op + l) = make_float2(acc[n8][rsel * 2] + bo,
                                                     acc[n8][rsel * 2 + 1] + bo);
                }
            }
        } else {
            // t >= 1: smem bounce -> coalesced 128B-row stores of U hi/lo
            const uint32_t bnc = sb + B_BNC + w * 2304;
            #pragma unroll
            for (int pl = 0; pl < 2; ++pl) {
                #pragma unroll
                for (int rsel = 0; rsel < 2; ++rsel)
                    #pragma unroll
                    for (int n8 = 0; n8 < 8; ++n8) {
                        __nv_bfloat16 h0, l0, h1, l1;
                        split2(acc[n8][rsel * 2], h0, l0);
                        split2(acc[n8][rsel * 2 + 1], h1, l1);
                        uint32_t pk = pl
                            ? ((uint32_t)__bfloat16_as_ushort(l0) | ((uint32_t)__bfloat16_as_ushort(l1) << 16))
                            : ((uint32_t)__bfloat16_as_ushort(h0) | ((uint32_t)__bfloat16_as_ushort(h1) << 16));
                        uint32_t ad = bnc + (uint32_t)((((lane >> 2) + rsel * 8) * 144 +
                                                        (n8 * 8 + (lane & 3) * 2) * 2));
                        asm volatile("st.shared.b32 [%0], %1;" :: "r"(ad), "r"(pk));
                    }
                __syncwarp();
                #pragma unroll
                for (int q = 0; q < 4; ++q) {
                    int r = q * 4 + (lane >> 3), c16 = lane & 7;
                    uint4 v;
                    asm volatile("ld.shared.v4.b32 {%0,%1,%2,%3}, [%4];"
                                 : "=r"(v.x), "=r"(v.y), "=r"(v.z), "=r"(v.w)
                                 : "r"(bnc + (uint32_t)(r * 144 + c16 * 16)));
                    const int o = (m0r + r) & 63;
                    char* up = (char*)(pl ? g_Ul : g_Uh) +
                        ((((size_t)b * 4 + (twarp - 1)) * 64 + o) * K_DIM + kcol) * 128 + c16 * 16;
                    *(uint4*)up = v;
                }
                __syncwarp();
            }
        }
    }
}

// ---------------------------------------------------------------- Stage C (unchanged from R11)
#define C_AH 0
#define C_AL 29952
#define C_BH 59904          // + oi*9216
#define C_BL 78336          // + oi*9216
#define CBUF 96768
#define C_SMEM (2 * CBUF)

__global__ __launch_bounds__(512)
void diffuse_mma(float* __restrict__ out) {
    extern __shared__ __align__(16) char smem[];
    const int tid = threadIdx.x, lane = tid & 31, w = tid >> 5;
    const int b = blockIdx.y, o0 = blockIdx.x * 2;
    const uint32_t sb = smem_u32(smem);

    float acc[2][8][4];
    #pragma unroll
    for (int oi = 0; oi < 2; ++oi)
        #pragma unroll
        for (int j = 0; j < 8; ++j)
            #pragma unroll
            for (int q = 0; q < 4; ++q) acc[oi][j][q] = 0.f;

    const int rowA = lane & 15, colA = (lane >> 4) * 8;
    const int rowB = lane & 15, colB = (lane >> 4) * 8;

    auto stage = [&](int s, int buf) {
        const int t = s >> 2, kc = s & 3;
        const char* Mh = (const char*)(g_Mh + ((size_t)(b * 4 + t) << 16));
        const char* Ml = (const char*)(g_Ml + ((size_t)(b * 4 + t) << 16));
        const uint32_t base = sb + buf * CBUF;
        #pragma unroll
        for (int it = 0; it < 7; ++it) {
            int e = tid + it * 512;
            if (e < 3328) {
                int pl = e / 1664, rem = e - pl * 1664;
                int r = rem >> 3, u = rem & 7;
                const char* src = (pl ? Ml : Mh) + r * 512 + kc * 128 + u * 16;
                cpa16(base + (pl ? C_AL : C_AH) + r * 144 + u * 16, src);
            }
        }
        #pragma unroll
        for (int it = 0; it < 4; ++it) {
            int e = tid + it * 512;
            int oi = e >> 10, rem = e & 1023;
            int pl = rem >> 9, r = (rem >> 3) & 63, u = rem & 7;
            int kg = kc * 64 + r;
            int sz = (kg < K_DIM) ? 16 : 0;
            const char* Ub = (const char*)(pl ? g_Ul : g_Uh) +
                ((((size_t)b * 4 + t) * 64 + o0 + oi) * K_DIM) * 128;
            size_t so = (size_t)((kg < K_DIM) ? kg : 0) * 128 + u * 16;
            cpa16z(base + (pl ? C_BL : C_BH) + oi * 9216 + r * 144 + u * 16, Ub + so, sz);
        }
        CP_COMMIT();
    };

    stage(0, 0);
    for (int s = 0; s < 16; ++s) {
        if (s + 1 < 16) { stage(s + 1, (s + 1) & 1); CP_WAIT1(); }
        else            { CP_WAIT0(); }
        __syncthreads();
        const uint32_t base = sb + (s & 1) * CBUF;
        if (w < 13) {
            const int c0max = ((s & 3) == 3) ? 16 : 64;
            for (int c0 = 0; c0 < c0max; c0 += 16) {
                uint32_t ah[4], al[4];
                uint32_t ra = base + C_AH + (uint32_t)(((w * 16 + rowA) * 72 + c0 + colA) * 2);
                ldsm4(ah, ra);
                ldsm4(al, ra + (C_AL - C_AH));
                #pragma unroll
                for (int oi = 0; oi < 2; ++oi) {
                    #pragma unroll
                    for (int p = 0; p < 4; ++p) {
                        uint32_t bh[4], bl[4];
                        uint32_t rb = base + C_BH + oi * 9216 +
                                      (uint32_t)(((c0 + rowB) * 72 + p * 16 + colB) * 2);
                        ldsm4t(bh, rb);
                        ldsm4t(bl, rb + (C_BL - C_BH));
                        #pragma unroll
                        for (int jj = 0; jj < 2; ++jj) {
                            float* d = acc[oi][p * 2 + jj];
                            mma16816(d, ah, &bh[jj * 2]);
                            mma16816(d, ah, &bl[jj * 2]);
                            mma16816(d, al, &bh[jj * 2]);
                        }
                    }
                }
            }
        }
        __syncthreads();
    }

    #pragma unroll
    for (int oi = 0; oi < 2; ++oi) {
        float* ob = out + ((size_t)b * 64 + o0 + oi) * KL;
        #pragma unroll
        for (int rsel = 0; rsel < 2; ++rsel) {
            const int j = w * 16 + (lane >> 2) + rsel * 8;
            if (j < K_DIM) {
                float* op = ob + (size_t)j * 64;
                #pragma unroll
                for (int n8 = 0; n8 < 8; ++n8) {
                    int l = n8 * 8 + (lane & 3) * 2;
                    float2 u = *(float2*)(op + l);
                    u.x += acc[oi][n8][rsel * 2];
                    u.y += acc[oi][n8][rsel * 2 + 1];
                    *(float2*)(op + l) = u;
                }
            }
        }
    }
}

// ----------------------------------------------------------------
extern "C" void kernel_launch(void* const* d_in, const int* in_sizes, int n_in,
                              void* d_out, int out_size) {
    (void)in_sizes; (void)n_in; (void)out_size;
    const float* x    = (const float*)d_in[0];
    const float* a0   = (const float*)d_in[1];
    const float* a1   = (const float*)d_in[2];
    const float* W    = (const float*)d_in[3];
    const float* bias = (const float*)d_in[4];
    float* out        = (float*)d_out;

    cudaFuncSetAttribute(square_mma, cudaFuncAttributeMaxDynamicSharedMemorySize, SQ_SMEM);
    cudaFuncSetAttribute(chanmix_mma, cudaFuncAttributeMaxDynamicSharedMemorySize, B_SMEM);
    cudaFuncSetAttribute(diffuse_mma, cudaFuncAttributeMaxDynamicSharedMemorySize, C_SMEM);

    splitM_kernel<<<8192, 256>>>(a0, a1);
    splitW_kernel<<<80, 256>>>(W);
    {
        dim3 grid(2, 2, B_DIM);    // nhalf x which x b
        square_mma<<<grid, 512, SQ_SMEM>>>();
    }
    {
        dim3 grid((K_DIM + KGRP - 1) / KGRP, B_DIM);   // 26 x 16
        chanmix_mma<<<grid, 640, B_SMEM>>>(x, bias, out);
    }
    {
        dim3 grid(C_DIM / 2, B_DIM);   // 32 x 16
        diffuse_mma<<<grid, 512, C_SMEM>>>(out);
    }
}

// round 14
// speedup vs baseline: 1.2038x; 1.0373x over previous
#include <cuda_runtime.h>
#include <cuda_bf16.h>
#include <cstdint>

#define B_DIM 16
#define C_DIM 64
#define K_DIM 207
#define L_DIM 64
#define KL    13248
#define C_IN  320
#define KSQ   (K_DIM * K_DIM)

// scratch
__device__ __nv_bfloat16 g_Mh[(size_t)B_DIM * 4 * 256 * 256];   // padded split M_t (0=A0,1=A0^2,2=A1,3=A1^2)
__device__ __nv_bfloat16 g_Ml[(size_t)B_DIM * 4 * 256 * 256];
__device__ __nv_bfloat16 g_Wh[320 * 64];                        // split W
__device__ __nv_bfloat16 g_Wl[320 * 64];
__device__ __nv_bfloat16 g_Uh[(size_t)B_DIM * 4 * C_DIM * K_DIM * L_DIM];  // [b][t][o][k][l]
__device__ __nv_bfloat16 g_Ul[(size_t)B_DIM * 4 * C_DIM * K_DIM * L_DIM];

__device__ __forceinline__ uint32_t smem_u32(const void* p) {
    uint32_t a;
    asm("{ .reg .u64 t; cvta.to.shared.u64 t, %1; cvt.u32.u64 %0, t; }" : "=r"(a) : "l"(p));
    return a;
}
__device__ __forceinline__ void split2(float v, __nv_bfloat16& h, __nv_bfloat16& l) {
    h = __float2bfloat16(v);
    l = __float2bfloat16(v - __bfloat162float(h));
}
__device__ __forceinline__ void ldsm4(uint32_t* r, uint32_t addr) {
    asm volatile("ldmatrix.sync.aligned.m8n8.x4.shared.b16 {%0,%1,%2,%3}, [%4];"
                 : "=r"(r[0]), "=r"(r[1]), "=r"(r[2]), "=r"(r[3]) : "r"(addr));
}
__device__ __forceinline__ void ldsm4t(uint32_t* r, uint32_t addr) {
    asm volatile("ldmatrix.sync.aligned.m8n8.x4.trans.shared.b16 {%0,%1,%2,%3}, [%4];"
                 : "=r"(r[0]), "=r"(r[1]), "=r"(r[2]), "=r"(r[3]) : "r"(addr));
}
__device__ __forceinline__ void mma16816(float* d, const uint32_t* a, const uint32_t* b) {
    asm volatile(
        "mma.sync.aligned.m16n8k16.row.col.f32.bf16.bf16.f32 "
        "{%0,%1,%2,%3}, {%4,%5,%6,%7}, {%8,%9}, {%0,%1,%2,%3};"
        : "+f"(d[0]), "+f"(d[1]), "+f"(d[2]), "+f"(d[3])
        : "r"(a[0]), "r"(a[1]), "r"(a[2]), "r"(a[3]), "r"(b[0]), "r"(b[1]));
}
__device__ __forceinline__ void cpa16(uint32_t dst, const void* src) {
    asm volatile("cp.async.cg.shared.global [%0], [%1], 16;" :: "r"(dst), "l"(src));
}
__device__ __forceinline__ void cpa16z(uint32_t dst, const void* src, int sz) {
    asm volatile("cp.async.cg.shared.global [%0], [%1], 16, %2;" :: "r"(dst), "l"(src), "r"(sz));
}
#define CP_COMMIT() asm volatile("cp.async.commit_group;" ::: "memory")
#define CP_WAIT0()  asm volatile("cp.async.wait_group 0;" ::: "memory")
#define CP_WAIT1()  asm volatile("cp.async.wait_group 1;" ::: "memory")

// ---------------------------------------------------------------- split A0/A1 into padded planes (slots 0, 2)
__global__ __launch_bounds__(256)
void splitM_kernel(const float* __restrict__ a0, const float* __restrict__ a1) {
    size_t e = (size_t)blockIdx.x * 256 + threadIdx.x;   // 2*16*65536 total
    int k = (int)(e & 255), j = (int)((e >> 8) & 255);
    int which = (int)((e >> 16) & 1), b = (int)(e >> 17);
    float v = 0.f;
    if (j < K_DIM && k < K_DIM) {
        const float* M = (which ? a1 : a0) + (size_t)b * KSQ;
        v = M[(size_t)j * K_DIM + k];
    }
    __nv_bfloat16 h, l; split2(v, h, l);
    size_t idx = (((size_t)(b * 4 + which * 2)) << 16) + ((size_t)j << 8) + k;
    g_Mh[idx] = h; g_Ml[idx] = l;
}

__global__ __launch_bounds__(256)
void splitW_kernel(const float* __restrict__ W) {
    int e = blockIdx.x * 256 + threadIdx.x;
    if (e < 320 * 64) {
        int m = e >> 6, c = e & 63;
        int t = m >> 6, o = m & 63;
        float v = W[(size_t)o * C_IN + t * 64 + c];
        __nv_bfloat16 h, l; split2(v, h, l);
        g_Wh[e] = h; g_Wl[e] = l;
    }
}

// ---------------------------------------------------------------- square via MMA: slot t+1 = (slot t)^2
// Block (nq, which, b): D[j, n] = sum_m A[j,m] A[m,n], n in [nq*64, +64)
// Double-buffered, 1 sync per kc stage.
#define SQ_AH 0
#define SQ_AL 36864
#define SQ_BH 73728
#define SQ_BL 82944
#define SQ_CBUF 92160
#define SQ_SMEM (2 * SQ_CBUF)

__global__ __launch_bounds__(512)
void square_mma() {
    extern __shared__ __align__(16) char smem[];
    const int tid = threadIdx.x, lane = tid & 31, w = tid >> 5;
    const int nq = blockIdx.x, which = blockIdx.y, b = blockIdx.z;
    const int tslot = which * 2;
    const uint32_t sb = smem_u32(smem);
    const char* Mh = (const char*)(g_Mh + ((size_t)(b * 4 + tslot) << 16));
    const char* Ml = (const char*)(g_Ml + ((size_t)(b * 4 + tslot) << 16));

    float acc[8][4];
    #pragma unroll
    for (int i = 0; i < 8; ++i)
        #pragma unroll
        for (int q = 0; q < 4; ++q) acc[i][q] = 0.f;

    const int rowA = lane & 15, colA = (lane >> 4) * 8;
    const int rowB = lane & 15, colB = (lane >> 4) * 8;

    auto stage = [&](int kc, int buf) {
        const uint32_t base = sb + buf * SQ_CBUF;
        // A: 2 planes x 256 rows x 8 x 16B
        #pragma unroll
        for (int it = 0; it < 8; ++it) {
            int e = tid + it * 512;
            int pl = e >> 11, rem = e & 2047;
            int r = rem >> 3, u = rem & 7;
            const char* src = (pl ? Ml : Mh) + r * 512 + kc * 128 + u * 16;
            cpa16(base + (pl ? SQ_AL : SQ_AH) + r * 144 + u * 16, src);
        }
        // B: 2 planes x 64 rows x 8 x 16B (n-chunk nq)
        #pragma unroll
        for (int it = 0; it < 2; ++it) {
            int e = tid + it * 512;
            int pl = e >> 9, rem = e & 511;
            int r = rem >> 3, u = rem & 7;
            const char* src = (pl ? Ml : Mh) + (kc * 64 + r) * 512 + nq * 128 + u * 16;
            cpa16(base + (pl ? SQ_BL : SQ_BH) + r * 144 + u * 16, src);
        }
        CP_COMMIT();
    };

    stage(0, 0);
    for (int kc = 0; kc < 4; ++kc) {
        CP_WAIT0();
        __syncthreads();
        if (kc + 1 < 4) stage(kc + 1, (kc + 1) & 1);
        const uint32_t base = sb + (kc & 1) * SQ_CBUF;
        #pragma unroll
        for (int c0 = 0; c0 < 64; c0 += 16) {
            uint32_t ah[4], al[4];
            uint32_t ra = base + SQ_AH + (uint32_t)(((w * 16 + rowA) * 72 + c0 + colA) * 2);
            ldsm4(ah, ra);
            ldsm4(al, ra + (SQ_AL - SQ_AH));
            #pragma unroll
            for (int p = 0; p < 4; ++p) {
                uint32_t bh[4], bl[4];
                uint32_t rb = base + SQ_BH + (uint32_t)(((c0 + rowB) * 72 + p * 16 + colB) * 2);
                ldsm4t(bh, rb);
                ldsm4t(bl, rb + (SQ_BL - SQ_BH));
                #pragma unroll
                for (int jj = 0; jj < 2; ++jj) {
                    float* d = acc[p * 2 + jj];
                    mma16816(d, ah, &bh[jj * 2]);
                    mma16816(d, ah, &bl[jj * 2]);
                    mma16816(d, al, &bh[jj * 2]);
                }
            }
        }
    }

    uint32_t* Dh = (uint32_t*)(g_Mh + ((size_t)(b * 4 + tslot + 1) << 16));
    uint32_t* Dl = (uint32_t*)(g_Ml + ((size_t)(b * 4 + tslot + 1) << 16));
    #pragma unroll
    for (int rsel = 0; rsel < 2; ++rsel) {
        const int j = w * 16 + (lane >> 2) + rsel * 8;
        #pragma unroll
        for (int i = 0; i < 8; ++i) {
            int n = nq * 64 + i * 8 + (lane & 3) * 2;
            __nv_bfloat16 h0, l0, h1, l1;
            split2(acc[i][rsel * 2], h0, l0);
            split2(acc[i][rsel * 2 + 1], h1, l1);
            Dh[(j * 256 + n) >> 1] = (uint32_t)__bfloat16_as_ushort(h0) |
                                     ((uint32_t)__bfloat16_as_ushort(h1) << 16);
            Dl[(j * 256 + n) >> 1] = (uint32_t)__bfloat16_as_ushort(l0) |
                                     ((uint32_t)__bfloat16_as_ushort(l1) << 16);
        }
    }
}

// ---------------------------------------------------------------- Stage B (unchanged from R13)
#define BW_H 0
#define BW_L 46080
#define BXF(buf)  (92160 + (buf) * 16384)
#define BXB(buf)  (124928 + (buf) * 18432)
#define B_BNC 161792                     // 20 warps x 2304 B
#define B_SMEM 207872
#define KGRP 8

__global__ __launch_bounds__(640)
void chanmix_mma(const float* __restrict__ x, const float* __restrict__ bias,
                 float* __restrict__ out) {
    extern __shared__ __align__(16) char smem[];
    const int tid = threadIdx.x, lane = tid & 31, w = tid >> 5;
    const int b = blockIdx.y;
    const int kbase = blockIdx.x * KGRP;
    const int G = (kbase + KGRP <= K_DIM) ? KGRP : (K_DIM - kbase);
    const uint32_t sb = smem_u32(smem);
    const float* xb = x + (size_t)b * C_DIM * KL;

    #pragma unroll
    for (int it = 0; it < 4; ++it) {
        int e = tid + it * 640;
        if (e < 2560) {
            int r = e >> 3, u = e & 7;
            cpa16(sb + BW_H + r * 144 + u * 16, (const char*)g_Wh + r * 128 + u * 16);
            cpa16(sb + BW_L + r * 144 + u * 16, (const char*)g_Wl + r * 128 + u * 16);
        }
    }
    CP_COMMIT();

    {
        int e = tid;
        #pragma unroll
        for (int it = 0; it < 2; ++it, e += 640)
            if (e < 1024) {
                int c = e >> 4, u = e & 15;
                cpa16(sb + BXF(0) + c * 256 + u * 16,
                      (const char*)(xb + (size_t)c * KL + (size_t)kbase * 64) + u * 16);
            }
        CP_COMMIT();
    }

    const int rowA = lane & 15, colA = (lane >> 4) * 8;
    const int rowB = lane & 15, colB = (lane >> 4) * 8;
    const int m0r = w * 16;
    const int twarp = m0r >> 6;

    for (int ki = 0; ki < G; ++ki) {
        const int kcol = kbase + ki;
        if (ki + 1 < G) {
            int e = tid;
            #pragma unroll
            for (int it = 0; it < 2; ++it, e += 640)
                if (e < 1024) {
                    int c = e >> 4, u = e & 15;
                    cpa16(sb + BXF((ki + 1) & 1) + c * 256 + u * 16,
                          (const char*)(xb + (size_t)c * KL + (size_t)(kcol + 1) * 64) + u * 16);
                }
            CP_COMMIT();
            CP_WAIT1();
        } else {
            CP_WAIT0();
        }
        __syncthreads();

        {
            const float4* fs = (const float4*)(smem + BXF(ki & 1));
            char* bh = smem + BXB(ki & 1);
            int e = tid;
            #pragma unroll
            for (int it = 0; it < 2; ++it, e += 640)
                if (e < 1024) {
                    int c = e >> 4, q = e & 15;
                    float4 v = fs[c * 16 + q];
                    __nv_bfloat16 h0, l0, h1, l1, h2, l2, h3, l3;
                    split2(v.x, h0, l0); split2(v.y, h1, l1);
                    split2(v.z, h2, l2); split2(v.w, h3, l3);
                    uint2 ph, pl;
                    ph.x = (uint32_t)__bfloat16_as_ushort(h0) | ((uint32_t)__bfloat16_as_ushort(h1) << 16);
                    ph.y = (uint32_t)__bfloat16_as_ushort(h2) | ((uint32_t)__bfloat16_as_ushort(h3) << 16);
                    pl.x = (uint32_t)__bfloat16_as_ushort(l0) | ((uint32_t)__bfloat16_as_ushort(l1) << 16);
                    pl.y = (uint32_t)__bfloat16_as_ushort(l2) | ((uint32_t)__bfloat16_as_ushort(l3) << 16);
                    *(uint2*)(bh + c * 144 + q * 8) = ph;
                    *(uint2*)(bh + 9216 + c * 144 + q * 8) = pl;
                }
        }
        __syncthreads();

        float acc[8][4];
        #pragma unroll
        for (int j = 0; j < 8; ++j)
            #pragma unroll
            for (int q = 0; q < 4; ++q) acc[j][q] = 0.f;

        const uint32_t xbase = sb + BXB(ki & 1);
        #pragma unroll
        for (int c0 = 0; c0 < 64; c0 += 16) {
            uint32_t ah[4], al[4];
            uint32_t ra = sb + BW_H + (uint32_t)(((m0r + rowA) * 72 + c0 + colA) * 2);
            ldsm4(ah, ra);
            ldsm4(al, ra + (BW_L - BW_H));
            #pragma unroll
            for (int p = 0; p < 4; ++p) {
                uint32_t bh[4], bl[4];
                uint32_t rb = xbase + (uint32_t)(((c0 + rowB) * 72 + p * 16 + colB) * 2);
                ldsm4t(bh, rb);
                ldsm4t(bl, rb + 9216);
                #pragma unroll
                for (int jj = 0; jj < 2; ++jj) {
                    float* d = acc[p * 2 + jj];
                    mma16816(d, ah, &bh[jj * 2]);
                    mma16816(d, ah, &bl[jj * 2]);
                    mma16816(d, al, &bh[jj * 2]);
                }
            }
        }

        if (twarp == 0) {
            #pragma unroll
            for (int rsel = 0; rsel < 2; ++rsel) {
                const int o = (m0r + (lane >> 2) + rsel * 8) & 63;
                const float bo = bias[o];
                float* op = out + ((size_t)b * 64 + o) * KL + (size_t)kcol * 64;
                #pragma unroll
                for (int n8 = 0; n8 < 8; ++n8) {
                    int l = n8 * 8 + (lane & 3) * 2;
                    *(float2*)(op + l) = make_float2(acc[n8][rsel * 2] + bo,
                                                     acc[n8][rsel * 2 + 1] + bo);
                }
            }
        } else {
            const uint32_t bnc = sb + B_BNC + w * 2304;
            #pragma unroll
            for (int pl = 0; pl < 2; ++pl) {
                #pragma unroll
                for (int rsel = 0; rsel < 2; ++rsel)
                    #pragma unroll
                    for (int n8 = 0; n8 < 8; ++n8) {
                        __nv_bfloat16 h0, l0, h1, l1;
                        split2(acc[n8][rsel * 2], h0, l0);
                        split2(acc[n8][rsel * 2 + 1], h1, l1);
                        uint32_t pk = pl
                            ? ((uint32_t)__bfloat16_as_ushort(l0) | ((uint32_t)__bfloat16_as_ushort(l1) << 16))
                            : ((uint32_t)__bfloat16_as_ushort(h0) | ((uint32_t)__bfloat16_as_ushort(h1) << 16));
                        uint32_t ad = bnc + (uint32_t)((((lane >> 2) + rsel * 8) * 144 +
                                                        (n8 * 8 + (lane & 3) * 2) * 2));
                        asm volatile("st.shared.b32 [%0], %1;" :: "r"(ad), "r"(pk));
                    }
                __syncwarp();
                #pragma unroll
                for (int q = 0; q < 4; ++q) {
                    int r = q * 4 + (lane >> 3), c16 = lane & 7;
                    uint4 v;
                    asm volatile("ld.shared.v4.b32 {%0,%1,%2,%3}, [%4];"
                                 : "=r"(v.x), "=r"(v.y), "=r"(v.z), "=r"(v.w)
                                 : "r"(bnc + (uint32_t)(r * 144 + c16 * 16)));
                    const int o = (m0r + r) & 63;
                    char* up = (char*)(pl ? g_Ul : g_Uh) +
                        ((((size_t)b * 4 + (twarp - 1)) * 64 + o) * K_DIM + kcol) * 128 + c16 * 16;
                    *(uint4*)up = v;
                }
                __syncwarp();
            }
        }
    }
}

// ---------------------------------------------------------------- Stage C
// Double-buffered, ONE sync per stage: wait -> sync -> issue stage(s+1) -> mma(s).
#define C_AH 0
#define C_AL 29952
#define C_BH 59904          // + oi*9216
#define C_BL 78336          // + oi*9216
#define CBUF 96768
#define C_SMEM (2 * CBUF)

__global__ __launch_bounds__(512)
void diffuse_mma(float* __restrict__ out) {
    extern __shared__ __align__(16) char smem[];
    const int tid = threadIdx.x, lane = tid & 31, w = tid >> 5;
    const int b = blockIdx.y, o0 = blockIdx.x * 2;
    const uint32_t sb = smem_u32(smem);

    float acc[2][8][4];
    #pragma unroll
    for (int oi = 0; oi < 2; ++oi)
        #pragma unroll
        for (int j = 0; j < 8; ++j)
            #pragma unroll
            for (int q = 0; q < 4; ++q) acc[oi][j][q] = 0.f;

    const int rowA = lane & 15, colA = (lane >> 4) * 8;
    const int rowB = lane & 15, colB = (lane >> 4) * 8;

    auto stage = [&](int s, int buf) {
        const int t = s >> 2, kc = s & 3;
        const char* Mh = (const char*)(g_Mh + ((size_t)(b * 4 + t) << 16));
        const char* Ml = (const char*)(g_Ml + ((size_t)(b * 4 + t) << 16));
        const uint32_t base = sb + buf * CBUF;
        #pragma unroll
        for (int it = 0; it < 7; ++it) {
            int e = tid + it * 512;
            if (e < 3328) {
                int pl = e / 1664, rem = e - pl * 1664;
                int r = rem >> 3, u = rem & 7;
                const char* src = (pl ? Ml : Mh) + r * 512 + kc * 128 + u * 16;
                cpa16(base + (pl ? C_AL : C_AH) + r * 144 + u * 16, src);
            }
        }
        #pragma unroll
        for (int it = 0; it < 4; ++it) {
            int e = tid + it * 512;
            int oi = e >> 10, rem = e & 1023;
            int pl = rem >> 9, r = (rem >> 3) & 63, u = rem & 7;
            int kg = kc * 64 + r;
            int sz = (kg < K_DIM) ? 16 : 0;
            const char* Ub = (const char*)(pl ? g_Ul : g_Uh) +
                ((((size_t)b * 4 + t) * 64 + o0 + oi) * K_DIM) * 128;
            size_t so = (size_t)((kg < K_DIM) ? kg : 0) * 128 + u * 16;
            cpa16z(base + (pl ? C_BL : C_BH) + oi * 9216 + r * 144 + u * 16, Ub + so, sz);
        }
        CP_COMMIT();
    };

    stage(0, 0);
    for (int s = 0; s < 16; ++s) {
        CP_WAIT0();
        __syncthreads();                 // stage s landed + mma(s-1) readers done
        if (s + 1 < 16) stage(s + 1, (s + 1) & 1);
        const uint32_t base = sb + (s & 1) * CBUF;
        if (w < 13) {
            const int c0max = ((s & 3) == 3) ? 16 : 64;
            for (int c0 = 0; c0 < c0max; c0 += 16) {
                uint32_t ah[4], al[4];
                uint32_t ra = base + C_AH + (uint32_t)(((w * 16 + rowA) * 72 + c0 + colA) * 2);
                ldsm4(ah, ra);
                ldsm4(al, ra + (C_AL - C_AH));
                #pragma unroll
                for (int oi = 0; oi < 2; ++oi) {
                    #pragma unroll
                    for (int p = 0; p < 4; ++p) {
                        uint32_t bh[4], bl[4];
                        uint32_t rb = base + C_BH + oi * 9216 +
                                      (uint32_t)(((c0 + rowB) * 72 + p * 16 + colB) * 2);
                        ldsm4t(bh, rb);
                        ldsm4t(bl, rb + (C_BL - C_BH));
                        #pragma unroll
                        for (int jj = 0; jj < 2; ++jj) {
                            float* d = acc[oi][p * 2 + jj];
                            mma16816(d, ah, &bh[jj * 2]);
                            mma16816(d, ah, &bl[jj * 2]);
                            mma16816(d, al, &bh[jj * 2]);
                        }
                    }
                }
            }
        }
    }

    #pragma unroll
    for (int oi = 0; oi < 2; ++oi) {
        float* ob = out + ((size_t)b * 64 + o0 + oi) * KL;
        #pragma unroll
        for (int rsel = 0; rsel < 2; ++rsel) {
            const int j = w * 16 + (lane >> 2) + rsel * 8;
            if (j < K_DIM) {
                float* op = ob + (size_t)j * 64;
                #pragma unroll
                for (int n8 = 0; n8 < 8; ++n8) {
                    int l = n8 * 8 + (lane & 3) * 2;
                    float2 u = *(float2*)(op + l);
                    u.x += acc[oi][n8][rsel * 2];
                    u.y += acc[oi][n8][rsel * 2 + 1];
                    *(float2*)(op + l) = u;
                }
            }
        }
    }
}

// ----------------------------------------------------------------
extern "C" void kernel_launch(void* const* d_in, const int* in_sizes, int n_in,
                              void* d_out, int out_size) {
    (void)in_sizes; (void)n_in; (void)out_size;
    const float* x    = (const float*)d_in[0];
    const float* a0   = (const float*)d_in[1];
    const float* a1   = (const float*)d_in[2];
    const float* W    = (const float*)d_in[3];
    const float* bias = (const float*)d_in[4];
    float* out        = (float*)d_out;

    cudaFuncSetAttribute(square_mma, cudaFuncAttributeMaxDynamicSharedMemorySize, SQ_SMEM);
    cudaFuncSetAttribute(chanmix_mma, cudaFuncAttributeMaxDynamicSharedMemorySize, B_SMEM);
    cudaFuncSetAttribute(diffuse_mma, cudaFuncAttributeMaxDynamicSharedMemorySize, C_SMEM);

    splitM_kernel<<<8192, 256>>>(a0, a1);
    splitW_kernel<<<80, 256>>>(W);
    {
        dim3 grid(4, 2, B_DIM);    // n-quarter x which x b = 128 blocks
        square_mma<<<grid, 512, SQ_SMEM>>>();
    }
    {
        dim3 grid((K_DIM + KGRP - 1) / KGRP, B_DIM);   // 26 x 16
        chanmix_mma<<<grid, 640, B_SMEM>>>(x, bias, out);
    }
    {
        dim3 grid(C_DIM / 2, B_DIM);   // 32 x 16
        diffuse_mma<<<grid, 512, C_SMEM>>>(out);
    }
}

// round 16
// speedup vs baseline: 1.2459x; 1.0350x over previous
#include <cuda_runtime.h>
#include <cuda_bf16.h>
#include <cstdint>

#define B_DIM 16
#define C_DIM 64
#define K_DIM 207
#define L_DIM 64
#define KL    13248
#define C_IN  320
#define KSQ   (K_DIM * K_DIM)

// scratch
__device__ __nv_bfloat16 g_Mh[(size_t)B_DIM * 4 * 256 * 256];   // padded split M_t (0=A0,1=A0^2,2=A1,3=A1^2)
__device__ __nv_bfloat16 g_Ml[(size_t)B_DIM * 4 * 256 * 256];
__device__ __nv_bfloat16 g_Wh[320 * 64];                        // split W
__device__ __nv_bfloat16 g_Wl[320 * 64];
__device__ __nv_bfloat16 g_Uh[(size_t)B_DIM * 4 * C_DIM * K_DIM * L_DIM];  // [b][t][o][k][l]
__device__ __nv_bfloat16 g_Ul[(size_t)B_DIM * 4 * C_DIM * K_DIM * L_DIM];

__device__ __forceinline__ uint32_t smem_u32(const void* p) {
    uint32_t a;
    asm("{ .reg .u64 t; cvta.to.shared.u64 t, %1; cvt.u32.u64 %0, t; }" : "=r"(a) : "l"(p));
    return a;
}
__device__ __forceinline__ void split2(float v, __nv_bfloat16& h, __nv_bfloat16& l) {
    h = __float2bfloat16(v);
    l = __float2bfloat16(v - __bfloat162float(h));
}
__device__ __forceinline__ void ldsm4(uint32_t* r, uint32_t addr) {
    asm volatile("ldmatrix.sync.aligned.m8n8.x4.shared.b16 {%0,%1,%2,%3}, [%4];"
                 : "=r"(r[0]), "=r"(r[1]), "=r"(r[2]), "=r"(r[3]) : "r"(addr));
}
__device__ __forceinline__ void ldsm4t(uint32_t* r, uint32_t addr) {
    asm volatile("ldmatrix.sync.aligned.m8n8.x4.trans.shared.b16 {%0,%1,%2,%3}, [%4];"
                 : "=r"(r[0]), "=r"(r[1]), "=r"(r[2]), "=r"(r[3]) : "r"(addr));
}
__device__ __forceinline__ void mma16816(float* d, const uint32_t* a, const uint32_t* b) {
    asm volatile(
        "mma.sync.aligned.m16n8k16.row.col.f32.bf16.bf16.f32 "
        "{%0,%1,%2,%3}, {%4,%5,%6,%7}, {%8,%9}, {%0,%1,%2,%3};"
        : "+f"(d[0]), "+f"(d[1]), "+f"(d[2]), "+f"(d[3])
        : "r"(a[0]), "r"(a[1]), "r"(a[2]), "r"(a[3]), "r"(b[0]), "r"(b[1]));
}
__device__ __forceinline__ void cpa16(uint32_t dst, const void* src) {
    asm volatile("cp.async.cg.shared.global [%0], [%1], 16;" :: "r"(dst), "l"(src));
}
__device__ __forceinline__ void cpa16z(uint32_t dst, const void* src, int sz) {
    asm volatile("cp.async.cg.shared.global [%0], [%1], 16, %2;" :: "r"(dst), "l"(src), "r"(sz));
}
#define CP_COMMIT() asm volatile("cp.async.commit_group;" ::: "memory")
#define CP_WAIT0()  asm volatile("cp.async.wait_group 0;" ::: "memory")
#define CP_WAIT1()  asm volatile("cp.async.wait_group 1;" ::: "memory")

// ---------------------------------------------------------------- split A0/A1 into padded planes (slots 0, 2)
__global__ __launch_bounds__(256)
void splitM_kernel(const float* __restrict__ a0, const float* __restrict__ a1) {
    size_t e = (size_t)blockIdx.x * 256 + threadIdx.x;   // 2*16*65536 total
    int k = (int)(e & 255), j = (int)((e >> 8) & 255);
    int which = (int)((e >> 16) & 1), b = (int)(e >> 17);
    float v = 0.f;
    if (j < K_DIM && k < K_DIM) {
        const float* M = (which ? a1 : a0) + (size_t)b * KSQ;
        v = M[(size_t)j * K_DIM + k];
    }
    __nv_bfloat16 h, l; split2(v, h, l);
    size_t idx = (((size_t)(b * 4 + which * 2)) << 16) + ((size_t)j << 8) + k;
    g_Mh[idx] = h; g_Ml[idx] = l;
}

__global__ __launch_bounds__(256)
void splitW_kernel(const float* __restrict__ W) {
    int e = blockIdx.x * 256 + threadIdx.x;
    if (e < 320 * 64) {
        int m = e >> 6, c = e & 63;
        int t = m >> 6, o = m & 63;
        float v = W[(size_t)o * C_IN + t * 64 + c];
        __nv_bfloat16 h, l; split2(v, h, l);
        g_Wh[e] = h; g_Wl[e] = l;
    }
}

// ---------------------------------------------------------------- square via MMA: slot t+1 = (slot t)^2
#define SQ_AH 0
#define SQ_AL 36864
#define SQ_BH 73728
#define SQ_BL 82944
#define SQ_CBUF 92160
#define SQ_SMEM (2 * SQ_CBUF)

__global__ __launch_bounds__(512)
void square_mma() {
    extern __shared__ __align__(16) char smem[];
    const int tid = threadIdx.x, lane = tid & 31, w = tid >> 5;
    const int nq = blockIdx.x, which = blockIdx.y, b = blockIdx.z;
    const int tslot = which * 2;
    const uint32_t sb = smem_u32(smem);
    const char* Mh = (const char*)(g_Mh + ((size_t)(b * 4 + tslot) << 16));
    const char* Ml = (const char*)(g_Ml + ((size_t)(b * 4 + tslot) << 16));

    float acc[8][4];
    #pragma unroll
    for (int i = 0; i < 8; ++i)
        #pragma unroll
        for (int q = 0; q < 4; ++q) acc[i][q] = 0.f;

    const int rowA = lane & 15, colA = (lane >> 4) * 8;
    const int rowB = lane & 15, colB = (lane >> 4) * 8;

    auto stage = [&](int kc, int buf) {
        const uint32_t base = sb + buf * SQ_CBUF;
        #pragma unroll
        for (int it = 0; it < 8; ++it) {
            int e = tid + it * 512;
            int pl = e >> 11, rem = e & 2047;
            int r = rem >> 3, u = rem & 7;
            const char* src = (pl ? Ml : Mh) + r * 512 + kc * 128 + u * 16;
            cpa16(base + (pl ? SQ_AL : SQ_AH) + r * 144 + u * 16, src);
        }
        #pragma unroll
        for (int it = 0; it < 2; ++it) {
            int e = tid + it * 512;
            int pl = e >> 9, rem = e & 511;
            int r = rem >> 3, u = rem & 7;
            const char* src = (pl ? Ml : Mh) + (kc * 64 + r) * 512 + nq * 128 + u * 16;
            cpa16(base + (pl ? SQ_BL : SQ_BH) + r * 144 + u * 16, src);
        }
        CP_COMMIT();
    };

    stage(0, 0);
    for (int kc = 0; kc < 4; ++kc) {
        CP_WAIT0();
        __syncthreads();
        if (kc + 1 < 4) stage(kc + 1, (kc + 1) & 1);
        const uint32_t base = sb + (kc & 1) * SQ_CBUF;
        #pragma unroll
        for (int c0 = 0; c0 < 64; c0 += 16) {
            uint32_t ah[4], al[4];
            uint32_t ra = base + SQ_AH + (uint32_t)(((w * 16 + rowA) * 72 + c0 + colA) * 2);
            ldsm4(ah, ra);
            ldsm4(al, ra + (SQ_AL - SQ_AH));
            #pragma unroll
            for (int p = 0; p < 4; ++p) {
                uint32_t bh[4], bl[4];
                uint32_t rb = base + SQ_BH + (uint32_t)(((c0 + rowB) * 72 + p * 16 + colB) * 2);
                ldsm4t(bh, rb);
                ldsm4t(bl, rb + (SQ_BL - SQ_BH));
                #pragma unroll
                for (int jj = 0; jj < 2; ++jj) {
                    float* d = acc[p * 2 + jj];
                    mma16816(d, ah, &bh[jj * 2]);
                    mma16816(d, ah, &bl[jj * 2]);
                    mma16816(d, al, &bh[jj * 2]);
                }
            }
        }
    }

    uint32_t* Dh = (uint32_t*)(g_Mh + ((size_t)(b * 4 + tslot + 1) << 16));
    uint32_t* Dl = (uint32_t*)(g_Ml + ((size_t)(b * 4 + tslot + 1) << 16));
    #pragma unroll
    for (int rsel = 0; rsel < 2; ++rsel) {
        const int j = w * 16 + (lane >> 2) + rsel * 8;
        #pragma unroll
        for (int i = 0; i < 8; ++i) {
            int n = nq * 64 + i * 8 + (lane & 3) * 2;
            __nv_bfloat16 h0, l0, h1, l1;
            split2(acc[i][rsel * 2], h0, l0);
            split2(acc[i][rsel * 2 + 1], h1, l1);
            Dh[(j * 256 + n) >> 1] = (uint32_t)__bfloat16_as_ushort(h0) |
                                     ((uint32_t)__bfloat16_as_ushort(h1) << 16);
            Dl[(j * 256 + n) >> 1] = (uint32_t)__bfloat16_as_ushort(l0) |
                                     ((uint32_t)__bfloat16_as_ushort(l1) << 16);
        }
    }
}

// ---------------------------------------------------------------- Stage B (unchanged from R13)
#define BW_H 0
#define BW_L 46080
#define BXF(buf)  (92160 + (buf) * 16384)
#define BXB(buf)  (124928 + (buf) * 18432)
#define B_BNC 161792                     // 20 warps x 2304 B
#define B_SMEM 207872
#define KGRP 8

__global__ __launch_bounds__(640)
void chanmix_mma(const float* __restrict__ x, const float* __restrict__ bias,
                 float* __restrict__ out) {
    extern __shared__ __align__(16) char smem[];
    const int tid = threadIdx.x, lane = tid & 31, w = tid >> 5;
    const int b = blockIdx.y;
    const int kbase = blockIdx.x * KGRP;
    const int G = (kbase + KGRP <= K_DIM) ? KGRP : (K_DIM - kbase);
    const uint32_t sb = smem_u32(smem);
    const float* xb = x + (size_t)b * C_DIM * KL;

    #pragma unroll
    for (int it = 0; it < 4; ++it) {
        int e = tid + it * 640;
        if (e < 2560) {
            int r = e >> 3, u = e & 7;
            cpa16(sb + BW_H + r * 144 + u * 16, (const char*)g_Wh + r * 128 + u * 16);
            cpa16(sb + BW_L + r * 144 + u * 16, (const char*)g_Wl + r * 128 + u * 16);
        }
    }
    CP_COMMIT();

    {
        int e = tid;
        #pragma unroll
        for (int it = 0; it < 2; ++it, e += 640)
            if (e < 1024) {
                int c = e >> 4, u = e & 15;
                cpa16(sb + BXF(0) + c * 256 + u * 16,
                      (const char*)(xb + (size_t)c * KL + (size_t)kbase * 64) + u * 16);
            }
        CP_COMMIT();
    }

    const int rowA = lane & 15, colA = (lane >> 4) * 8;
    const int rowB = lane & 15, colB = (lane >> 4) * 8;
    const int m0r = w * 16;
    const int twarp = m0r >> 6;

    for (int ki = 0; ki < G; ++ki) {
        const int kcol = kbase + ki;
        if (ki + 1 < G) {
            int e = tid;
            #pragma unroll
            for (int it = 0; it < 2; ++it, e += 640)
                if (e < 1024) {
                    int c = e >> 4, u = e & 15;
                    cpa16(sb + BXF((ki + 1) & 1) + c * 256 + u * 16,
                          (const char*)(xb + (size_t)c * KL + (size_t)(kcol + 1) * 64) + u * 16);
                }
            CP_COMMIT();
            CP_WAIT1();
        } else {
            CP_WAIT0();
        }
        __syncthreads();

        {
            const float4* fs = (const float4*)(smem + BXF(ki & 1));
            char* bh = smem + BXB(ki & 1);
            int e = tid;
            #pragma unroll
            for (int it = 0; it < 2; ++it, e += 640)
                if (e < 1024) {
                    int c = e >> 4, q = e & 15;
                    float4 v = fs[c * 16 + q];
                    __nv_bfloat16 h0, l0, h1, l1, h2, l2, h3, l3;
                    split2(v.x, h0, l0); split2(v.y, h1, l1);
                    split2(v.z, h2, l2); split2(v.w, h3, l3);
                    uint2 ph, pl;
                    ph.x = (uint32_t)__bfloat16_as_ushort(h0) | ((uint32_t)__bfloat16_as_ushort(h1) << 16);
                    ph.y = (uint32_t)__bfloat16_as_ushort(h2) | ((uint32_t)__bfloat16_as_ushort(h3) << 16);
                    pl.x = (uint32_t)__bfloat16_as_ushort(l0) | ((uint32_t)__bfloat16_as_ushort(l1) << 16);
                    pl.y = (uint32_t)__bfloat16_as_ushort(l2) | ((uint32_t)__bfloat16_as_ushort(l3) << 16);
                    *(uint2*)(bh + c * 144 + q * 8) = ph;
                    *(uint2*)(bh + 9216 + c * 144 + q * 8) = pl;
                }
        }
        __syncthreads();

        float acc[8][4];
        #pragma unroll
        for (int j = 0; j < 8; ++j)
            #pragma unroll
            for (int q = 0; q < 4; ++q) acc[j][q] = 0.f;

        const uint32_t xbase = sb + BXB(ki & 1);
        #pragma unroll
        for (int c0 = 0; c0 < 64; c0 += 16) {
            uint32_t ah[4], al[4];
            uint32_t ra = sb + BW_H + (uint32_t)(((m0r + rowA) * 72 + c0 + colA) * 2);
            ldsm4(ah, ra);
            ldsm4(al, ra + (BW_L - BW_H));
            #pragma unroll
            for (int p = 0; p < 4; ++p) {
                uint32_t bh[4], bl[4];
                uint32_t rb = xbase + (uint32_t)(((c0 + rowB) * 72 + p * 16 + colB) * 2);
                ldsm4t(bh, rb);
                ldsm4t(bl, rb + 9216);
                #pragma unroll
                for (int jj = 0; jj < 2; ++jj) {
                    float* d = acc[p * 2 + jj];
                    mma16816(d, ah, &bh[jj * 2]);
                    mma16816(d, ah, &bl[jj * 2]);
                    mma16816(d, al, &bh[jj * 2]);
                }
            }
        }

        if (twarp == 0) {
            #pragma unroll
            for (int rsel = 0; rsel < 2; ++rsel) {
                const int o = (m0r + (lane >> 2) + rsel * 8) & 63;
                const float bo = bias[o];
                float* op = out + ((size_t)b * 64 + o) * KL + (size_t)kcol * 64;
                #pragma unroll
                for (int n8 = 0; n8 < 8; ++n8) {
                    int l = n8 * 8 + (lane & 3) * 2;
                    *(float2*)(op + l) = make_float2(acc[n8][rsel * 2] + bo,
                                                     acc[n8][rsel * 2 + 1] + bo);
                }
            }
        } else {
            const uint32_t bnc = sb + B_BNC + w * 2304;
            #pragma unroll
            for (int pl = 0; pl < 2; ++pl) {
                #pragma unroll
                for (int rsel = 0; rsel < 2; ++rsel)
                    #pragma unroll
                    for (int n8 = 0; n8 < 8; ++n8) {
                        __nv_bfloat16 h0, l0, h1, l1;
                        split2(acc[n8][rsel * 2], h0, l0);
                        split2(acc[n8][rsel * 2 + 1], h1, l1);
                        uint32_t pk = pl
                            ? ((uint32_t)__bfloat16_as_ushort(l0) | ((uint32_t)__bfloat16_as_ushort(l1) << 16))
                            : ((uint32_t)__bfloat16_as_ushort(h0) | ((uint32_t)__bfloat16_as_ushort(h1) << 16));
                        uint32_t ad = bnc + (uint32_t)((((lane >> 2) + rsel * 8) * 144 +
                                                        (n8 * 8 + (lane & 3) * 2) * 2));
                        asm volatile("st.shared.b32 [%0], %1;" :: "r"(ad), "r"(pk));
                    }
                __syncwarp();
                #pragma unroll
                for (int q = 0; q < 4; ++q) {
                    int r = q * 4 + (lane >> 3), c16 = lane & 7;
                    uint4 v;
                    asm volatile("ld.shared.v4.b32 {%0,%1,%2,%3}, [%4];"
                                 : "=r"(v.x), "=r"(v.y), "=r"(v.z), "=r"(v.w)
                                 : "r"(bnc + (uint32_t)(r * 144 + c16 * 16)));
                    const int o = (m0r + r) & 63;
                    char* up = (char*)(pl ? g_Ul : g_Uh) +
                        ((((size_t)b * 4 + (twarp - 1)) * 64 + o) * K_DIM + kcol) * 128 + c16 * 16;
                    *(uint4*)up = v;
                }
                __syncwarp();
            }
        }
    }
}

// ---------------------------------------------------------------- Stage C
// 832 threads = 26 warps: warp = (jt 0..12) x (oi 0..1), 16 j-rows x 1 o each.
// Double-buffered, one sync per stage.
#define C_AH 0
#define C_AL 29952
#define C_BH 59904          // + oi*9216
#define C_BL 78336          // + oi*9216
#define CBUF 96768
#define C_SMEM (2 * CBUF)

__global__ __launch_bounds__(832)
void diffuse_mma(float* __restrict__ out) {
    extern __shared__ __align__(16) char smem[];
    const int tid = threadIdx.x, lane = tid & 31, w = tid >> 5;
    const int b = blockIdx.y, o0 = blockIdx.x * 2;
    const uint32_t sb = smem_u32(smem);
    const int jt = w >> 1, oi = w & 1;   // valid for w < 26

    float acc[8][4];
    #pragma unroll
    for (int j = 0; j < 8; ++j)
        #pragma unroll
        for (int q = 0; q < 4; ++q) acc[j][q] = 0.f;

    const int rowA = lane & 15, colA = (lane >> 4) * 8;
    const int rowB = lane & 15, colB = (lane >> 4) * 8;

    auto stage = [&](int s, int buf) {
        const int t = s >> 2, kc = s & 3;
        const char* Mh = (const char*)(g_Mh + ((size_t)(b * 4 + t) << 16));
        const char* Ml = (const char*)(g_Ml + ((size_t)(b * 4 + t) << 16));
        const uint32_t base = sb + buf * CBUF;
        // A: 2 planes x 208 rows x 8 x 16B = 3328 xfers (4 x 832 exact)
        #pragma unroll
        for (int it = 0; it < 4; ++it) {
            int e = tid + it * 832;
            int pl = e / 1664, rem = e - pl * 1664;
            int r = rem >> 3, u = rem & 7;
            const char* src = (pl ? Ml : Mh) + r * 512 + kc * 128 + u * 16;
            cpa16(base + (pl ? C_AL : C_AH) + r * 144 + u * 16, src);
        }
        // B: 2 oi x 2 planes x 64 rows x 8 x 16B = 2048 xfers, zfill pad
        #pragma unroll
        for (int it = 0; it < 3; ++it) {
            int e = tid + it * 832;
            if (e < 2048) {
                int oo = e >> 10, rem = e & 1023;
                int pl = rem >> 9, r = (rem >> 3) & 63, u = rem & 7;
                int kg = kc * 64 + r;
                int sz = (kg < K_DIM) ? 16 : 0;
                const char* Ub = (const char*)(pl ? g_Ul : g_Uh) +
                    ((((size_t)b * 4 + t) * 64 + o0 + oo) * K_DIM) * 128;
                size_t so = (size_t)((kg < K_DIM) ? kg : 0) * 128 + u * 16;
                cpa16z(base + (pl ? C_BL : C_BH) + oo * 9216 + r * 144 + u * 16, Ub + so, sz);
            }
        }
        CP_COMMIT();
    };

    stage(0, 0);
    for (int s = 0; s < 16; ++s) {
        CP_WAIT0();
        __syncthreads();                 // stage s landed + mma(s-1) readers done
        if (s + 1 < 16) stage(s + 1, (s + 1) & 1);
        const uint32_t base = sb + (s & 1) * CBUF;
        if (w < 26) {
            const int c0max = ((s & 3) == 3) ? 16 : 64;
            for (int c0 = 0; c0 < c0max; c0 += 16) {
                uint32_t ah[4], al[4];
                uint32_t ra = base + C_AH + (uint32_t)(((jt * 16 + rowA) * 72 + c0 + colA) * 2);
                ldsm4(ah, ra);
                ldsm4(al, ra + (C_AL - C_AH));
                #pragma unroll
                for (int p = 0; p < 4; ++p) {
                    uint32_t bh[4], bl[4];
                    uint32_t rb = base + C_BH + oi * 9216 +
                                  (uint32_t)(((c0 + rowB) * 72 + p * 16 + colB) * 2);
                    ldsm4t(bh, rb);
                    ldsm4t(bl, rb + (C_BL - C_BH));
                    #pragma unroll
                    for (int jj = 0; jj < 2; ++jj) {
                        float* d = acc[p * 2 + jj];
                        mma16816(d, ah, &bh[jj * 2]);
                        mma16816(d, ah, &bl[jj * 2]);
                        mma16816(d, al, &bh[jj * 2]);
                    }
                }
            }
        }
    }

    if (w < 26) {
        float* ob = out + ((size_t)b * 64 + o0 + oi) * KL;
        #pragma unroll
        for (int rsel = 0; rsel < 2; ++rsel) {
            const int j = jt * 16 + (lane >> 2) + rsel * 8;
            if (j < K_DIM) {
                float* op = ob + (size_t)j * 64;
                #pragma unroll
                for (int n8 = 0; n8 < 8; ++n8) {
                    int l = n8 * 8 + (lane & 3) * 2;
                    float2 u = *(float2*)(op + l);
                    u.x += acc[n8][rsel * 2];
                    u.y += acc[n8][rsel * 2 + 1];
                    *(float2*)(op + l) = u;
                }
            }
        }
    }
}

// ----------------------------------------------------------------
extern "C" void kernel_launch(void* const* d_in, const int* in_sizes, int n_in,
                              void* d_out, int out_size) {
    (void)in_sizes; (void)n_in; (void)out_size;
    const float* x    = (const float*)d_in[0];
    const float* a0   = (const float*)d_in[1];
    const float* a1   = (const float*)d_in[2];
    const float* W    = (const float*)d_in[3];
    const float* bias = (const float*)d_in[4];
    float* out        = (float*)d_out;

    cudaFuncSetAttribute(square_mma, cudaFuncAttributeMaxDynamicSharedMemorySize, SQ_SMEM);
    cudaFuncSetAttribute(chanmix_mma, cudaFuncAttributeMaxDynamicSharedMemorySize, B_SMEM);
    cudaFuncSetAttribute(diffuse_mma, cudaFuncAttributeMaxDynamicSharedMemorySize, C_SMEM);

    splitM_kernel<<<8192, 256>>>(a0, a1);
    splitW_kernel<<<80, 256>>>(W);
    {
        dim3 grid(4, 2, B_DIM);    // n-quarter x which x b = 128 blocks
        square_mma<<<grid, 512, SQ_SMEM>>>();
    }
    {
        dim3 grid((K_DIM + KGRP - 1) / KGRP, B_DIM);   // 26 x 16
        chanmix_mma<<<grid, 640, B_SMEM>>>(x, bias, out);
    }
    {
        dim3 grid(C_DIM / 2, B_DIM);   // 32 x 16
        diffuse_mma<<<grid, 832, C_SMEM>>>(out);
    }
}